// round 1
// baseline (speedup 1.0000x reference)
#include <cuda_runtime.h>

// Problem constants
#define BB 8192      // batch rows
#define NN 4096      // feature dim
#define BLK 64       // Monarch block size (P=Q=R=S=64, K=L=64 blocks)
#define PAD 68       // smem row pad (floats): 68*4=272B, 16B-aligned for float4

// 128 MB scratch for the intermediate (B, 4096) tensor.
__device__ float g_scratch[(size_t)BB * NN];

// One 64x64x64 GEMM per CTA: C_tile[row][col] = sum_p A[row, j*64+p] * W[j, col, p]
//   blockIdx.x -> row tile (64 rows), blockIdx.y = j (block index k or l)
// A: (B, 4096) row-major. W: (64, 64, 64) = W[j*4096 + col*64 + p].
// Writes C[(row)*4096 + j*64 + col]  (natural layout, coalesced float4).
// Safe when A == C: each CTA reads exactly the 64x64 region it later writes,
// and all global reads complete before the __syncthreads() preceding writes.
__global__ __launch_bounds__(256) void gemm64(const float* A, const float* W, float* C) {
    __shared__ __align__(16) float As[BLK][PAD];   // As[p][row]
    __shared__ __align__(16) float Ws[BLK][PAD];   // Ws[p][col]

    const int m0  = blockIdx.x * BLK;
    const int j   = blockIdx.y;
    const int tid = threadIdx.x;

    // ---- load phase (coalesced global reads) ----
    {
        const int p  = tid & 63;
        const int r0 = tid >> 6;                 // 0..3
        const float* Ag = A + (size_t)m0 * NN + j * BLK;
        const float* Wg = W + (size_t)j * (BLK * BLK);
#pragma unroll
        for (int i = 0; i < 16; i++) {
            const int row = r0 + i * 4;          // 0..63
            As[p][row] = Ag[(size_t)row * NN + p];
            Ws[p][row] = Wg[row * BLK + p];      // row = output col index, p = reduction
        }
    }
    __syncthreads();

    // ---- main loop: 4x4 microtile per thread ----
    const int tq  = tid & 15;                    // 16 col-tiles
    const int tm  = tid >> 4;                    // 16 row-tiles
    const int q0  = tq * 4;
    const int mi0 = tm * 4;

    float acc[4][4] = {};
#pragma unroll 8
    for (int p = 0; p < BLK; p++) {
        const float4 av = *(const float4*)(&As[p][mi0]);
        const float4 bv = *(const float4*)(&Ws[p][q0]);
        const float a[4] = {av.x, av.y, av.z, av.w};
        const float w[4] = {bv.x, bv.y, bv.z, bv.w};
#pragma unroll
        for (int ii = 0; ii < 4; ii++)
#pragma unroll
            for (int jj = 0; jj < 4; jj++)
                acc[ii][jj] = fmaf(a[ii], w[jj], acc[ii][jj]);
    }

    // ---- write (coalesced float4) ----
#pragma unroll
    for (int ii = 0; ii < 4; ii++) {
        float4 v = make_float4(acc[ii][0], acc[ii][1], acc[ii][2], acc[ii][3]);
        *(float4*)(C + (size_t)(m0 + mi0 + ii) * NN + j * BLK + q0) = v;
    }
}

// Per-row 64x64 transpose: out[b, i*64 + j] = in[b, j*64 + i].
// One CTA per batch row; fully coalesced both directions; safe in-place.
__global__ __launch_bounds__(256) void trans64(const float* in, float* out) {
    __shared__ float sm[BLK][BLK + 1];
    const int b   = blockIdx.x;
    const int tid = threadIdx.x;
    const float* ip = in  + (size_t)b * NN;
    float*       op = out + (size_t)b * NN;

#pragma unroll
    for (int i = 0; i < 16; i++) {
        const int t = tid + i * 256;
        sm[t & 63][t >> 6] = ip[t];              // store transposed, conflict-free
    }
    __syncthreads();
#pragma unroll
    for (int i = 0; i < 16; i++) {
        const int t = tid + i * 256;
        op[t] = sm[t >> 6][t & 63];              // conflict-free read
    }
}

extern "C" void kernel_launch(void* const* d_in, const int* in_sizes, int n_in,
                              void* d_out, int out_size) {
    const float* x  = (const float*)d_in[0];   // (8192, 4096)
    const float* w1 = (const float*)d_in[1];   // (64, 64, 64)
    const float* w2 = (const float*)d_in[2];   // (64, 64, 64)
    float* out = (float*)d_out;

    float* scratch = nullptr;
    cudaGetSymbolAddress((void**)&scratch, g_scratch);

    dim3 ggrid(BB / BLK, BLK);   // (128, 64)
    dim3 gblk(256);

    // Stage 1: out1[b, k*64+q] = sum_p x[b, k*64+p] * w1[k, q, p]
    gemm64<<<ggrid, gblk>>>(x, w1, scratch);
    // Permutation: (b, r*64+l) -> (b, l*64+r)   [r=k, l=q]
    trans64<<<BB, 256>>>(scratch, scratch);
    // Stage 2: out2[b, l*64+s] = sum_r perm[b, l*64+r] * w2[l, s, r]
    gemm64<<<ggrid, gblk>>>(scratch, w2, scratch);
    // Final permutation: out[b, s*64+l] = out2[b, l*64+s]
    trans64<<<BB, 256>>>(scratch, out);
}

// round 3
// speedup vs baseline: 1.5885x; 1.5885x over previous
#include <cuda_runtime.h>
#include <cstdint>

#define BB 8192      // batch rows
#define NN 4096      // feature dim
#define PADF 68      // smem row pitch in floats (16B-aligned, conflict-free)

// 128 MB scratch for the intermediate (B, 4096) tensor.
__device__ float g_scratch[(size_t)BB * NN];

__device__ __forceinline__ uint32_t f2tf32(float f) {
    uint32_t r;
    asm("cvt.rna.tf32.f32 %0, %1;" : "=r"(r) : "f"(f));
    return r;
}

__device__ __forceinline__ void mma16n8k8(float* d, const uint32_t* a,
                                          uint32_t b0, uint32_t b1) {
    asm volatile(
        "mma.sync.aligned.m16n8k8.row.col.f32.tf32.tf32.f32 "
        "{%0,%1,%2,%3}, {%4,%5,%6,%7}, {%8,%9}, {%0,%1,%2,%3};"
        : "+f"(d[0]), "+f"(d[1]), "+f"(d[2]), "+f"(d[3])
        : "r"(a[0]), "r"(a[1]), "r"(a[2]), "r"(a[3]), "r"(b0), "r"(b1));
}

// ---------------------------------------------------------------------------
// Tensor-core GEMM (mma.sync tf32): one CTA = 128 rows x one 64x64 block (j).
//   C[(m0+row)*4096 + j*64 + q] = sum_p A[(m0+row)*4096 + j*64 + p] * W[j,q,p]
// A smem: As[row][k] (tf32 bits), 128x64, pitch 68.
// W smem: Ws[q][p]   (tf32 bits),  64x64, pitch 68.   (q = n, p = k)
// 4 warps; warp tile 32(M) x 64(N); m16n8k8 fragments loaded by direct LDS
// (layouts per PTX ISA: A a0..a3 = [g][t],[g+8][t],[g][t+4],[g+8][t+4];
//  B b0,b1 = [k=t][n=g],[k=t+4][n=g]; C c0..c3 = rows g/g+8, cols 2t,2t+1).
// Safe in-place (A==C): all global reads happen in the load phase; writes
// come after the full K loop over smem data only.
// ---------------------------------------------------------------------------
__global__ __launch_bounds__(128) void gemm_mma(const float* __restrict__ A,
                                                const float* __restrict__ W,
                                                float* __restrict__ C) {
    extern __shared__ __align__(16) uint32_t sm[];
    uint32_t* As = sm;                 // 128 * 68
    uint32_t* Ws = sm + 128 * PADF;    //  64 * 68

    const int tid  = threadIdx.x;
    const int warp = tid >> 5;
    const int lane = tid & 31;
    const int g    = lane >> 2;        // group id (0..7)
    const int t    = lane & 3;         // thread in group (0..3)
    const int m0   = blockIdx.x * 128;
    const int j    = blockIdx.y;

    // ---- load A tile (coalesced float4), convert to tf32 ----
    {
        const float* Ag = A + (size_t)m0 * NN + j * 64;
#pragma unroll
        for (int i = 0; i < 16; i++) {
            const int g4  = tid + i * 128;     // 0..2047
            const int row = g4 >> 4;
            const int c4  = (g4 & 15) * 4;
            const float4 v = *(const float4*)(Ag + (size_t)row * NN + c4);
            uint32_t* d = As + row * PADF + c4;
            d[0] = f2tf32(v.x); d[1] = f2tf32(v.y);
            d[2] = f2tf32(v.z); d[3] = f2tf32(v.w);
        }
    }
    // ---- load W tile ----
    {
        const float* Wg = W + (size_t)j * 4096;
#pragma unroll
        for (int i = 0; i < 8; i++) {
            const int g4 = tid + i * 128;      // 0..1023
            const int q  = g4 >> 4;
            const int c4 = (g4 & 15) * 4;
            const float4 v = *(const float4*)(Wg + q * 64 + c4);
            uint32_t* d = Ws + q * PADF + c4;
            d[0] = f2tf32(v.x); d[1] = f2tf32(v.y);
            d[2] = f2tf32(v.z); d[3] = f2tf32(v.w);
        }
    }
    __syncthreads();

    // ---- main loop ----
    float acc[2][8][4] = {};
    const int rb0 = warp * 32;
#pragma unroll
    for (int ks = 0; ks < 8; ks++) {
        const int k0 = ks * 8;
        uint32_t a[2][4];
#pragma unroll
        for (int mi = 0; mi < 2; mi++) {
            const int rb = rb0 + mi * 16;
            a[mi][0] = As[(rb + g)     * PADF + k0 + t];
            a[mi][1] = As[(rb + g + 8) * PADF + k0 + t];
            a[mi][2] = As[(rb + g)     * PADF + k0 + t + 4];
            a[mi][3] = As[(rb + g + 8) * PADF + k0 + t + 4];
        }
#pragma unroll
        for (int ni = 0; ni < 8; ni++) {
            const uint32_t b0 = Ws[(ni * 8 + g) * PADF + k0 + t];
            const uint32_t b1 = Ws[(ni * 8 + g) * PADF + k0 + t + 4];
            mma16n8k8(acc[0][ni], a[0], b0, b1);
            mma16n8k8(acc[1][ni], a[1], b0, b1);
        }
    }

    // ---- epilogue: direct float2 stores (sector-exact) ----
    float* Cg = C + (size_t)m0 * NN + j * 64;
#pragma unroll
    for (int mi = 0; mi < 2; mi++) {
        const int r0 = rb0 + mi * 16 + g;
#pragma unroll
        for (int ni = 0; ni < 8; ni++) {
            const int col = ni * 8 + t * 2;
            *(float2*)(Cg + (size_t)r0 * NN + col) =
                make_float2(acc[mi][ni][0], acc[mi][ni][1]);
            *(float2*)(Cg + (size_t)(r0 + 8) * NN + col) =
                make_float2(acc[mi][ni][2], acc[mi][ni][3]);
        }
    }
}

// ---------------------------------------------------------------------------
// Per-row 64x64 transpose: out[b, i*64 + j] = in[b, j*64 + i]. In-place safe.
// ---------------------------------------------------------------------------
__global__ __launch_bounds__(256) void trans64(const float* __restrict__ in,
                                               float* __restrict__ out) {
    __shared__ float smt[64][65];
    const int b   = blockIdx.x;
    const int tid = threadIdx.x;
    const float* ip = in  + (size_t)b * NN;
    float*       op = out + (size_t)b * NN;

#pragma unroll
    for (int i = 0; i < 16; i++) {
        const int t = tid + i * 256;
        smt[t & 63][t >> 6] = ip[t];
    }
    __syncthreads();
#pragma unroll
    for (int i = 0; i < 16; i++) {
        const int t = tid + i * 256;
        op[t] = smt[t >> 6][t & 63];
    }
}

extern "C" void kernel_launch(void* const* d_in, const int* in_sizes, int n_in,
                              void* d_out, int out_size) {
    const float* x  = (const float*)d_in[0];   // (8192, 4096)
    const float* w1 = (const float*)d_in[1];   // (64, 64, 64)
    const float* w2 = (const float*)d_in[2];   // (64, 64, 64)
    float* out = (float*)d_out;

    float* scratch = nullptr;
    cudaGetSymbolAddress((void**)&scratch, g_scratch);

    const int smem_bytes = (128 * PADF + 64 * PADF) * 4;   // 52224
    cudaFuncSetAttribute(gemm_mma, cudaFuncAttributeMaxDynamicSharedMemorySize,
                         smem_bytes);

    dim3 ggrid(BB / 128, 64);   // (64, 64)

    // Stage 1: out1[b, k*64+q] = sum_p x[b, k*64+p] * w1[k, q, p]
    gemm_mma<<<ggrid, 128, smem_bytes>>>(x, w1, scratch);
    // Permutation: (b, r*64+l) -> (b, l*64+r)
    trans64<<<BB, 256>>>(scratch, scratch);
    // Stage 2: out2[b, l*64+s] = sum_r perm[b, l*64+r] * w2[l, s, r]
    gemm_mma<<<ggrid, 128, smem_bytes>>>(scratch, w2, scratch);
    // Final permutation: out[b, s*64+l] = out2[b, l*64+s]
    trans64<<<BB, 256>>>(scratch, out);
}